// round 16
// baseline (speedup 1.0000x reference)
#include <cuda_runtime.h>

#define Lq 128
#define Bq 128
#define Dq 1024
#define Aq 1024
#define Hq 2048
#define KSPLIT 16
#define KC (Dq / KSPLIT)   // 64 k per split block (4 k-tiles of 16)

typedef unsigned long long ull;

// Scratch (device globals: allocation-free, graph-safe)
__device__ float g_projp[KSPLIT * Bq * Aq];  // split-K partials (8MB, L2-resident)
__device__ float g_proj[Bq * Aq];            // reduced proj + bias
__device__ float g_eT[Bq * Lq];              // UNNORMALIZED e~ = exp(score+b)*mask, (B,L)

__device__ __forceinline__ float tanh_fast(float x) {
    float y;
    asm("tanh.approx.f32 %0, %1;" : "=f"(y) : "f"(x));
    return y;
}
__device__ __forceinline__ ull pack2(float x, float y) {
    ull r;
    asm("mov.b64 %0, {%1, %2};" : "=l"(r) : "f"(x), "f"(y));
    return r;
}
__device__ __forceinline__ void unpack2(ull v, float& lo, float& hi) {
    asm("mov.b64 {%0, %1}, %2;" : "=f"(lo), "=f"(hi) : "l"(v));
}
__device__ __forceinline__ ull ffma2(ull a, ull b, ull c) {
    ull d;
    asm("fma.rn.f32x2 %0, %1, %2, %3;" : "=l"(d) : "l"(a), "l"(b), "l"(c));
    return d;
}

// ---------------------------------------------------------------------------
// K1: proj partials. 128(m) x 64(n) tile, KT=16, split-K=16, grid (16,16).
// KEY CHANGE: B is stored in smem PRE-DUPLICATED as f32x2 pairs (Bsd), so
// the inner loop has ZERO pack2 ops: per kk = 4 LDS.128 + 16 ffma2
// (80% fma issue density vs ~60% before). Thread's n-columns are
// {tx*2, tx*2+1, tx*2+32, tx*2+33} so both Bsd LDS.128 are dense
// 16-lane x 16B (conflict-free); the naive tx*4 map would 8-way conflict.
// ---------------------------------------------------------------------------
__global__ void __launch_bounds__(256, 1) k_proj(const float* __restrict__ S,
                                                 const float* __restrict__ W) {
    const int a0    = blockIdx.x * 64;
    const int kbase = blockIdx.y * KC;

    __shared__ float As[16][132];   // [k][m] floats
    __shared__ ull   Bsd[16][66];   // [k][n] duplicated pairs (b,b)

    const int t  = threadIdx.x;
    const int ar = t >> 1;          // A loader row (0..127)
    const int ac = (t & 1) * 8;     // A loader k-offset (0 or 8)
    const int br = t >> 2;          // B loader row (0..63)
    const int bc = (t & 3) * 4;     // B loader k-offset
    const int tx = t & 15;
    const int ty = t >> 4;
    const int m0 = ty * 8;          // 8 m-rows (4 packed pairs)
    const int n0 = tx * 2;          // n-cols: n0, n0+1, n0+32, n0+33

    ull acc[4][4];                  // [mi][nj]
#pragma unroll
    for (int i = 0; i < 4; ++i)
#pragma unroll
        for (int j = 0; j < 4; ++j) acc[i][j] = 0ull;

#pragma unroll
    for (int kt = 0; kt < KC; kt += 16) {
        const int k0 = kbase + kt;
        float4 av0 = *(const float4*)(S + (size_t)ar * Dq + k0 + ac);
        float4 av1 = *(const float4*)(S + (size_t)ar * Dq + k0 + ac + 4);
        float4 bv  = *(const float4*)(W + (size_t)(a0 + br) * Dq + k0 + bc);
        __syncthreads();
        As[ac + 0][ar] = av0.x;  As[ac + 1][ar] = av0.y;
        As[ac + 2][ar] = av0.z;  As[ac + 3][ar] = av0.w;
        As[ac + 4][ar] = av1.x;  As[ac + 5][ar] = av1.y;
        As[ac + 6][ar] = av1.z;  As[ac + 7][ar] = av1.w;
        Bsd[bc + 0][br] = pack2(bv.x, bv.x);
        Bsd[bc + 1][br] = pack2(bv.y, bv.y);
        Bsd[bc + 2][br] = pack2(bv.z, bv.z);
        Bsd[bc + 3][br] = pack2(bv.w, bv.w);
        __syncthreads();
#pragma unroll
        for (int kk = 0; kk < 16; ++kk) {
            ulonglong2 a01 = *(const ulonglong2*)&As[kk][m0];
            ulonglong2 a23 = *(const ulonglong2*)&As[kk][m0 + 4];
            ulonglong2 blo = *(const ulonglong2*)&Bsd[kk][n0];
            ulonglong2 bhi = *(const ulonglong2*)&Bsd[kk][n0 + 32];
            acc[0][0] = ffma2(a01.x, blo.x, acc[0][0]);
            acc[0][1] = ffma2(a01.x, blo.y, acc[0][1]);
            acc[0][2] = ffma2(a01.x, bhi.x, acc[0][2]);
            acc[0][3] = ffma2(a01.x, bhi.y, acc[0][3]);
            acc[1][0] = ffma2(a01.y, blo.x, acc[1][0]);
            acc[1][1] = ffma2(a01.y, blo.y, acc[1][1]);
            acc[1][2] = ffma2(a01.y, bhi.x, acc[1][2]);
            acc[1][3] = ffma2(a01.y, bhi.y, acc[1][3]);
            acc[2][0] = ffma2(a23.x, blo.x, acc[2][0]);
            acc[2][1] = ffma2(a23.x, blo.y, acc[2][1]);
            acc[2][2] = ffma2(a23.x, bhi.x, acc[2][2]);
            acc[2][3] = ffma2(a23.x, bhi.y, acc[2][3]);
            acc[3][0] = ffma2(a23.y, blo.x, acc[3][0]);
            acc[3][1] = ffma2(a23.y, blo.y, acc[3][1]);
            acc[3][2] = ffma2(a23.y, bhi.x, acc[3][2]);
            acc[3][3] = ffma2(a23.y, bhi.y, acc[3][3]);
        }
    }

    // store: per m-pair, float2 at cols (n0,n0+1) and (n0+32,n0+33)
    float* base = g_projp + (size_t)blockIdx.y * Bq * Aq + a0;
#pragma unroll
    for (int mi = 0; mi < 4; ++mi) {
        const int m = m0 + 2 * mi;
        float2 lo_m, lo_m1, hi_m, hi_m1;
        unpack2(acc[mi][0], lo_m.x, lo_m1.x);
        unpack2(acc[mi][1], lo_m.y, lo_m1.y);
        unpack2(acc[mi][2], hi_m.x, hi_m1.x);
        unpack2(acc[mi][3], hi_m.y, hi_m1.y);
        *(float2*)(base + (size_t)m * Aq + n0)            = lo_m;
        *(float2*)(base + (size_t)(m + 1) * Aq + n0)      = lo_m1;
        *(float2*)(base + (size_t)m * Aq + n0 + 32)       = hi_m;
        *(float2*)(base + (size_t)(m + 1) * Aq + n0 + 32) = hi_m1;
    }
}

// ---------------------------------------------------------------------------
// K2: g_proj = sum_z partials + bias.
// EXACTLY covers Bq*Aq = 131072 floats = 32768 float4 = 128 blocks x 256 thr.
// Partials are L2-resident (8MB).
// ---------------------------------------------------------------------------
__global__ void __launch_bounds__(256) k_reduce(const float* __restrict__ bsa) {
    const int idx = (blockIdx.x * 256 + threadIdx.x) * 4;
    const int a   = idx & (Aq - 1);
    float4 s = *(const float4*)(bsa + a);
#pragma unroll
    for (int z = 0; z < KSPLIT; ++z) {
        float4 p = *(const float4*)(g_projp + (size_t)z * Bq * Aq + idx);
        s.x += p.x;  s.y += p.y;  s.z += p.z;  s.w += p.w;
    }
    *(float4*)(g_proj + idx) = s;
}

// ---------------------------------------------------------------------------
// K3: e~[b,l] = exp(b_a1 + sum_a w_a1[a]*tanh(proj[b,a]+uh[l,b,a])) * mask
// Warp per (l,b); 8 warps share one b. Softmax numerator fused in epilogue.
// Grid: B * L/8 = 2048 blocks, 256 threads.
// ---------------------------------------------------------------------------
__global__ void __launch_bounds__(256) k_scores(const float* __restrict__ uh,
                                                const float* __restrict__ w1,
                                                const float* __restrict__ mask,
                                                const float* __restrict__ ba1) {
    const int b  = blockIdx.x >> 4;
    const int l0 = (blockIdx.x & 15) << 3;
    __shared__ float ps[Aq];
    __shared__ float ws[Aq];
    const int t  = threadIdx.x;
    const int i4 = t * 4;

    *(float4*)&ps[i4] = *(const float4*)(g_proj + (size_t)b * Aq + i4);
    *(float4*)&ws[i4] = *(const float4*)(w1 + i4);
    __syncthreads();

    const int w    = t >> 5;
    const int lane = t & 31;
    const int l    = l0 + w;
    const float* u = uh + (size_t)(l * Bq + b) * Aq;

    float acc = 0.f;
#pragma unroll
    for (int i = 0; i < 8; ++i) {
        int idx = i * 128 + lane * 4;
        float4 u4 = __ldcs((const float4*)(u + idx));
        float4 p4 = *(const float4*)&ps[idx];
        float4 w4 = *(const float4*)&ws[idx];
        acc = fmaf(w4.x, tanh_fast(p4.x + u4.x), acc);
        acc = fmaf(w4.y, tanh_fast(p4.y + u4.y), acc);
        acc = fmaf(w4.z, tanh_fast(p4.z + u4.z), acc);
        acc = fmaf(w4.w, tanh_fast(p4.w + u4.w), acc);
    }
#pragma unroll
    for (int off = 16; off; off >>= 1)
        acc += __shfl_xor_sync(0xffffffffu, acc, off);
    if (lane == 0)
        g_eT[b * Lq + l] = __expf(acc + ba1[0]) * mask[l * Bq + b];
}

// ---------------------------------------------------------------------------
// K4: attend[b,h] = (1/S_b) * sum_l e~[l,b] * xs_h[l,b,h];  S_b = sum_l e~.
// Block = (b, 256-wide h chunk), 256 threads = 64 cols(x4) * 4 l-groups.
// h0==0 blocks also write normalized e_ij. Grid: B*8 = 1024 blocks.
// ---------------------------------------------------------------------------
__global__ void __launch_bounds__(256) k_attend(const float* __restrict__ xs,
                                                float* __restrict__ e_out,
                                                float* __restrict__ out) {
    const int b  = blockIdx.x >> 3;
    const int h0 = (blockIdx.x & 7) * 256;
    const int t  = threadIdx.x;

    __shared__ float  es[Lq];
    __shared__ float  red[4];
    __shared__ float4 pacc[256];

    float ev = 0.f;
    if (t < 128) ev = g_eT[b * Lq + t];
    float v = ev;
#pragma unroll
    for (int off = 16; off; off >>= 1)
        v += __shfl_xor_sync(0xffffffffu, v, off);
    if (t < 128) {
        if ((t & 31) == 0) red[t >> 5] = v;
        es[t] = ev;
    }
    __syncthreads();
    const float inv = 1.f / ((red[0] + red[1]) + (red[2] + red[3]));
    if (h0 == 0 && t < 128) e_out[t * Bq + b] = es[t] * inv;

    const int col = t & 63;
    const int g   = t >> 6;
    const float* base = xs + (size_t)(g * 32) * Bq * Hq +
                        (size_t)b * Hq + h0 + col * 4;
    float4 a0 = make_float4(0.f, 0.f, 0.f, 0.f);
    float4 a1 = make_float4(0.f, 0.f, 0.f, 0.f);
#pragma unroll
    for (int i = 0; i < 32; i += 2) {
        float4 v0 = __ldcs((const float4*)(base + (size_t)(i + 0) * Bq * Hq));
        float4 v1 = __ldcs((const float4*)(base + (size_t)(i + 1) * Bq * Hq));
        float e0 = es[g * 32 + i + 0];
        float e1 = es[g * 32 + i + 1];
        a0.x = fmaf(e0, v0.x, a0.x);  a0.y = fmaf(e0, v0.y, a0.y);
        a0.z = fmaf(e0, v0.z, a0.z);  a0.w = fmaf(e0, v0.w, a0.w);
        a1.x = fmaf(e1, v1.x, a1.x);  a1.y = fmaf(e1, v1.y, a1.y);
        a1.z = fmaf(e1, v1.z, a1.z);  a1.w = fmaf(e1, v1.w, a1.w);
    }
    a0.x += a1.x;  a0.y += a1.y;  a0.z += a1.z;  a0.w += a1.w;
    pacc[t] = a0;
    __syncthreads();
    if (g == 0) {
        float4 p1 = pacc[col + 64];
        float4 p2 = pacc[col + 128];
        float4 p3 = pacc[col + 192];
        a0.x = ((a0.x + p1.x) + (p2.x + p3.x)) * inv;
        a0.y = ((a0.y + p1.y) + (p2.y + p3.y)) * inv;
        a0.z = ((a0.z + p1.z) + (p2.z + p3.z)) * inv;
        a0.w = ((a0.w + p1.w) + (p2.w + p3.w)) * inv;
        *(float4*)(out + (size_t)b * Hq + h0 + col * 4) = a0;
    }
}

// ---------------------------------------------------------------------------
extern "C" void kernel_launch(void* const* d_in, const int* in_sizes, int n_in,
                              void* d_out, int out_size) {
    const float* s_tm1 = (const float*)d_in[0];
    const float* xs_h  = (const float*)d_in[1];
    const float* uh    = (const float*)d_in[2];
    const float* mask  = (const float*)d_in[3];
    const float* W_sa  = (const float*)d_in[4];
    const float* b_sa  = (const float*)d_in[5];
    const float* w_a1  = (const float*)d_in[6];
    const float* b_a1  = (const float*)d_in[7];
    float* out = (float*)d_out;  // [0 : L*B) = e_ij, [L*B : ) = attend

    k_proj<<<dim3(16, KSPLIT), 256>>>(s_tm1, W_sa);
    k_reduce<<<128, 256>>>(b_sa);
    k_scores<<<2048, 256>>>(uh, w_a1, mask, b_a1);
    k_attend<<<1024, 256>>>(xs_h, out, out + Lq * Bq);
}

// round 17
// speedup vs baseline: 1.0303x; 1.0303x over previous
#include <cuda_runtime.h>

#define Lq 128
#define Bq 128
#define Dq 1024
#define Aq 1024
#define Hq 2048
#define KSPLIT 16
#define KC (Dq / KSPLIT)   // 64 k per split block (4 k-tiles of 16)

typedef unsigned long long ull;

// Scratch (device globals: allocation-free, graph-safe)
__device__ float g_projp[KSPLIT * Bq * Aq];  // split-K partials (8MB, L2-resident)
__device__ float g_proj[Bq * Aq];            // reduced proj + bias
__device__ float g_eT[Bq * Lq];              // UNNORMALIZED e~ = exp(score+b)*mask, (B,L)

__device__ __forceinline__ float tanh_fast(float x) {
    float y;
    asm("tanh.approx.f32 %0, %1;" : "=f"(y) : "f"(x));
    return y;
}
__device__ __forceinline__ ull pack2(float x, float y) {
    ull r;
    asm("mov.b64 %0, {%1, %2};" : "=l"(r) : "f"(x), "f"(y));
    return r;
}
__device__ __forceinline__ void unpack2(ull v, float& lo, float& hi) {
    asm("mov.b64 {%0, %1}, %2;" : "=f"(lo), "=f"(hi) : "l"(v));
}
__device__ __forceinline__ ull ffma2(ull a, ull b, ull c) {
    ull d;
    asm("fma.rn.f32x2 %0, %1, %2, %3;" : "=l"(d) : "l"(a), "l"(b), "l"(c));
    return d;
}

// ---------------------------------------------------------------------------
// K1: proj partials. 128(m) x 128(n) tile, 8x8 register tile per thread
// (32 f32x2 accumulators), KT=16, split-K=16. Grid (8, 16) = 128 blocks.
// Per kk: 4 LDS.128 + 8 pack2 + 32 ffma2 = 44 issue slots vs 64 fma-pipe
// cycles -> fma-pipe-bound per warp; crossbar ~38% (A broadcast, B dense);
// gmem prefetched into registers across k-tiles (one sync per tile).
// ---------------------------------------------------------------------------
__global__ void __launch_bounds__(256, 1) k_proj(const float* __restrict__ S,
                                                 const float* __restrict__ W) {
    const int a0    = blockIdx.x * 128;
    const int kbase = blockIdx.y * KC;

    __shared__ float As[16][132];   // [k][m]
    __shared__ float Bs[16][132];   // [k][n]

    const int t  = threadIdx.x;
    const int lr = t >> 1;          // loader row (0..127) for both A and B
    const int lc = (t & 1) * 8;     // loader k-offset (0 or 8)
    const int tx = t & 15;          // n-group
    const int ty = t >> 4;          // m-group
    const int m0 = ty * 8;
    const int n0 = tx * 8;

    ull acc[4][8];                  // [m-pair][n]
#pragma unroll
    for (int i = 0; i < 4; ++i)
#pragma unroll
        for (int j = 0; j < 8; ++j) acc[i][j] = 0ull;

    float4 sv0, sv1, wv0, wv1;

    // prologue: load tile 0
    {
        const int k0 = kbase;
        sv0 = *(const float4*)(S + (size_t)lr * Dq + k0 + lc);
        sv1 = *(const float4*)(S + (size_t)lr * Dq + k0 + lc + 4);
        wv0 = *(const float4*)(W + (size_t)(a0 + lr) * Dq + k0 + lc);
        wv1 = *(const float4*)(W + (size_t)(a0 + lr) * Dq + k0 + lc + 4);
    }

#pragma unroll
    for (int kt = 0; kt < 4; ++kt) {
        // store staged tile to smem
        As[lc + 0][lr] = sv0.x;  As[lc + 1][lr] = sv0.y;
        As[lc + 2][lr] = sv0.z;  As[lc + 3][lr] = sv0.w;
        As[lc + 4][lr] = sv1.x;  As[lc + 5][lr] = sv1.y;
        As[lc + 6][lr] = sv1.z;  As[lc + 7][lr] = sv1.w;
        Bs[lc + 0][lr] = wv0.x;  Bs[lc + 1][lr] = wv0.y;
        Bs[lc + 2][lr] = wv0.z;  Bs[lc + 3][lr] = wv0.w;
        Bs[lc + 4][lr] = wv1.x;  Bs[lc + 5][lr] = wv1.y;
        Bs[lc + 6][lr] = wv1.z;  Bs[lc + 7][lr] = wv1.w;
        __syncthreads();

        // prefetch next tile from gmem (latency covered by compute below)
        if (kt < 3) {
            const int k0 = kbase + (kt + 1) * 16;
            sv0 = *(const float4*)(S + (size_t)lr * Dq + k0 + lc);
            sv1 = *(const float4*)(S + (size_t)lr * Dq + k0 + lc + 4);
            wv0 = *(const float4*)(W + (size_t)(a0 + lr) * Dq + k0 + lc);
            wv1 = *(const float4*)(W + (size_t)(a0 + lr) * Dq + k0 + lc + 4);
        }

#pragma unroll
        for (int kk = 0; kk < 16; ++kk) {
            ulonglong2 a01 = *(const ulonglong2*)&As[kk][m0];
            ulonglong2 a23 = *(const ulonglong2*)&As[kk][m0 + 4];
            float4 bq0 = *(const float4*)&Bs[kk][n0];
            float4 bq1 = *(const float4*)&Bs[kk][n0 + 4];
            ull b0 = pack2(bq0.x, bq0.x), b1 = pack2(bq0.y, bq0.y);
            ull b2 = pack2(bq0.z, bq0.z), b3 = pack2(bq0.w, bq0.w);
            ull b4 = pack2(bq1.x, bq1.x), b5 = pack2(bq1.y, bq1.y);
            ull b6 = pack2(bq1.z, bq1.z), b7 = pack2(bq1.w, bq1.w);
            acc[0][0] = ffma2(a01.x, b0, acc[0][0]);
            acc[0][1] = ffma2(a01.x, b1, acc[0][1]);
            acc[0][2] = ffma2(a01.x, b2, acc[0][2]);
            acc[0][3] = ffma2(a01.x, b3, acc[0][3]);
            acc[0][4] = ffma2(a01.x, b4, acc[0][4]);
            acc[0][5] = ffma2(a01.x, b5, acc[0][5]);
            acc[0][6] = ffma2(a01.x, b6, acc[0][6]);
            acc[0][7] = ffma2(a01.x, b7, acc[0][7]);
            acc[1][0] = ffma2(a01.y, b0, acc[1][0]);
            acc[1][1] = ffma2(a01.y, b1, acc[1][1]);
            acc[1][2] = ffma2(a01.y, b2, acc[1][2]);
            acc[1][3] = ffma2(a01.y, b3, acc[1][3]);
            acc[1][4] = ffma2(a01.y, b4, acc[1][4]);
            acc[1][5] = ffma2(a01.y, b5, acc[1][5]);
            acc[1][6] = ffma2(a01.y, b6, acc[1][6]);
            acc[1][7] = ffma2(a01.y, b7, acc[1][7]);
            acc[2][0] = ffma2(a23.x, b0, acc[2][0]);
            acc[2][1] = ffma2(a23.x, b1, acc[2][1]);
            acc[2][2] = ffma2(a23.x, b2, acc[2][2]);
            acc[2][3] = ffma2(a23.x, b3, acc[2][3]);
            acc[2][4] = ffma2(a23.x, b4, acc[2][4]);
            acc[2][5] = ffma2(a23.x, b5, acc[2][5]);
            acc[2][6] = ffma2(a23.x, b6, acc[2][6]);
            acc[2][7] = ffma2(a23.x, b7, acc[2][7]);
            acc[3][0] = ffma2(a23.y, b0, acc[3][0]);
            acc[3][1] = ffma2(a23.y, b1, acc[3][1]);
            acc[3][2] = ffma2(a23.y, b2, acc[3][2]);
            acc[3][3] = ffma2(a23.y, b3, acc[3][3]);
            acc[3][4] = ffma2(a23.y, b4, acc[3][4]);
            acc[3][5] = ffma2(a23.y, b5, acc[3][5]);
            acc[3][6] = ffma2(a23.y, b6, acc[3][6]);
            acc[3][7] = ffma2(a23.y, b7, acc[3][7]);
        }
        if (kt < 3) __syncthreads();   // protect smem before next store phase
    }

    // store partials: 4 m-pairs x 8 n  ->  per pair two rows, 2 float4 each
    float* base = g_projp + (size_t)blockIdx.y * Bq * Aq + a0 + n0;
#pragma unroll
    for (int mi = 0; mi < 4; ++mi) {
        const int m = m0 + 2 * mi;
        float4 lo0, lo1, hi0, hi1;
        unpack2(acc[mi][0], lo0.x, hi0.x);
        unpack2(acc[mi][1], lo0.y, hi0.y);
        unpack2(acc[mi][2], lo0.z, hi0.z);
        unpack2(acc[mi][3], lo0.w, hi0.w);
        unpack2(acc[mi][4], lo1.x, hi1.x);
        unpack2(acc[mi][5], lo1.y, hi1.y);
        unpack2(acc[mi][6], lo1.z, hi1.z);
        unpack2(acc[mi][7], lo1.w, hi1.w);
        *(float4*)(base + (size_t)m * Aq)           = lo0;
        *(float4*)(base + (size_t)m * Aq + 4)       = lo1;
        *(float4*)(base + (size_t)(m + 1) * Aq)     = hi0;
        *(float4*)(base + (size_t)(m + 1) * Aq + 4) = hi1;
    }
}

// ---------------------------------------------------------------------------
// K2: g_proj = sum_z partials + bias.
// EXACTLY covers Bq*Aq = 131072 floats = 32768 float4 = 128 blocks x 256 thr.
// ---------------------------------------------------------------------------
__global__ void __launch_bounds__(256) k_reduce(const float* __restrict__ bsa) {
    const int idx = (blockIdx.x * 256 + threadIdx.x) * 4;
    const int a   = idx & (Aq - 1);
    float4 s = *(const float4*)(bsa + a);
#pragma unroll
    for (int z = 0; z < KSPLIT; ++z) {
        float4 p = *(const float4*)(g_projp + (size_t)z * Bq * Aq + idx);
        s.x += p.x;  s.y += p.y;  s.z += p.z;  s.w += p.w;
    }
    *(float4*)(g_proj + idx) = s;
}

// ---------------------------------------------------------------------------
// K3: e~[b,l] = exp(b_a1 + sum_a w_a1[a]*tanh(proj[b,a]+uh[l,b,a])) * mask
// Warp per (l,b); 8 warps share one b. Grid: 2048 blocks, 256 threads.
// ---------------------------------------------------------------------------
__global__ void __launch_bounds__(256) k_scores(const float* __restrict__ uh,
                                                const float* __restrict__ w1,
                                                const float* __restrict__ mask,
                                                const float* __restrict__ ba1) {
    const int b  = blockIdx.x >> 4;
    const int l0 = (blockIdx.x & 15) << 3;
    __shared__ float ps[Aq];
    __shared__ float ws[Aq];
    const int t  = threadIdx.x;
    const int i4 = t * 4;

    *(float4*)&ps[i4] = *(const float4*)(g_proj + (size_t)b * Aq + i4);
    *(float4*)&ws[i4] = *(const float4*)(w1 + i4);
    __syncthreads();

    const int w    = t >> 5;
    const int lane = t & 31;
    const int l    = l0 + w;
    const float* u = uh + (size_t)(l * Bq + b) * Aq;

    float acc = 0.f;
#pragma unroll
    for (int i = 0; i < 8; ++i) {
        int idx = i * 128 + lane * 4;
        float4 u4 = __ldcs((const float4*)(u + idx));
        float4 p4 = *(const float4*)&ps[idx];
        float4 w4 = *(const float4*)&ws[idx];
        acc = fmaf(w4.x, tanh_fast(p4.x + u4.x), acc);
        acc = fmaf(w4.y, tanh_fast(p4.y + u4.y), acc);
        acc = fmaf(w4.z, tanh_fast(p4.z + u4.z), acc);
        acc = fmaf(w4.w, tanh_fast(p4.w + u4.w), acc);
    }
#pragma unroll
    for (int off = 16; off; off >>= 1)
        acc += __shfl_xor_sync(0xffffffffu, acc, off);
    if (lane == 0)
        g_eT[b * Lq + l] = __expf(acc + ba1[0]) * mask[l * Bq + b];
}

// ---------------------------------------------------------------------------
// K4: attend[b,h] = (1/S_b) * sum_l e~[l,b] * xs_h[l,b,h];  S_b = sum_l e~.
// Block = (b, 256-wide h chunk), 256 threads. h0==0 blocks write e_ij.
// Grid: B*8 = 1024 blocks.
// ---------------------------------------------------------------------------
__global__ void __launch_bounds__(256) k_attend(const float* __restrict__ xs,
                                                float* __restrict__ e_out,
                                                float* __restrict__ out) {
    const int b  = blockIdx.x >> 3;
    const int h0 = (blockIdx.x & 7) * 256;
    const int t  = threadIdx.x;

    __shared__ float  es[Lq];
    __shared__ float  red[4];
    __shared__ float4 pacc[256];

    float ev = 0.f;
    if (t < 128) ev = g_eT[b * Lq + t];
    float v = ev;
#pragma unroll
    for (int off = 16; off; off >>= 1)
        v += __shfl_xor_sync(0xffffffffu, v, off);
    if (t < 128) {
        if ((t & 31) == 0) red[t >> 5] = v;
        es[t] = ev;
    }
    __syncthreads();
    const float inv = 1.f / ((red[0] + red[1]) + (red[2] + red[3]));
    if (h0 == 0 && t < 128) e_out[t * Bq + b] = es[t] * inv;

    const int col = t & 63;
    const int g   = t >> 6;
    const float* base = xs + (size_t)(g * 32) * Bq * Hq +
                        (size_t)b * Hq + h0 + col * 4;
    float4 a0 = make_float4(0.f, 0.f, 0.f, 0.f);
    float4 a1 = make_float4(0.f, 0.f, 0.f, 0.f);
#pragma unroll
    for (int i = 0; i < 32; i += 2) {
        float4 v0 = __ldcs((const float4*)(base + (size_t)(i + 0) * Bq * Hq));
        float4 v1 = __ldcs((const float4*)(base + (size_t)(i + 1) * Bq * Hq));
        float e0 = es[g * 32 + i + 0];
        float e1 = es[g * 32 + i + 1];
        a0.x = fmaf(e0, v0.x, a0.x);  a0.y = fmaf(e0, v0.y, a0.y);
        a0.z = fmaf(e0, v0.z, a0.z);  a0.w = fmaf(e0, v0.w, a0.w);
        a1.x = fmaf(e1, v1.x, a1.x);  a1.y = fmaf(e1, v1.y, a1.y);
        a1.z = fmaf(e1, v1.z, a1.z);  a1.w = fmaf(e1, v1.w, a1.w);
    }
    a0.x += a1.x;  a0.y += a1.y;  a0.z += a1.z;  a0.w += a1.w;
    pacc[t] = a0;
    __syncthreads();
    if (g == 0) {
        float4 p1 = pacc[col + 64];
        float4 p2 = pacc[col + 128];
        float4 p3 = pacc[col + 192];
        a0.x = ((a0.x + p1.x) + (p2.x + p3.x)) * inv;
        a0.y = ((a0.y + p1.y) + (p2.y + p3.y)) * inv;
        a0.z = ((a0.z + p1.z) + (p2.z + p3.z)) * inv;
        a0.w = ((a0.w + p1.w) + (p2.w + p3.w)) * inv;
        *(float4*)(out + (size_t)b * Hq + h0 + col * 4) = a0;
    }
}

// ---------------------------------------------------------------------------
extern "C" void kernel_launch(void* const* d_in, const int* in_sizes, int n_in,
                              void* d_out, int out_size) {
    const float* s_tm1 = (const float*)d_in[0];
    const float* xs_h  = (const float*)d_in[1];
    const float* uh    = (const float*)d_in[2];
    const float* mask  = (const float*)d_in[3];
    const float* W_sa  = (const float*)d_in[4];
    const float* b_sa  = (const float*)d_in[5];
    const float* w_a1  = (const float*)d_in[6];
    const float* b_a1  = (const float*)d_in[7];
    float* out = (float*)d_out;  // [0 : L*B) = e_ij, [L*B : ) = attend

    k_proj<<<dim3(8, KSPLIT), 256>>>(s_tm1, W_sa);
    k_reduce<<<128, 256>>>(b_sa);
    k_scores<<<2048, 256>>>(uh, w_a1, mask, b_a1);
    k_attend<<<1024, 256>>>(xs_h, out, out + Lq * Bq);
}